// round 15
// baseline (speedup 1.0000x reference)
#include <cuda_runtime.h>

// Problem constants (fixed by the reference: B=2, C=8, L=256, D=128)
#define B_  2
#define C_  8
#define L_  256
#define D_  128
#define TILE 32          // 32x32 output tile per block
#define THREADS 128      // 16 (tj: col-pairs) x 8 (ti2: row-quads); 4x2 out each

__device__ __forceinline__ float rcp_fast(float x) {
    float y; asm("rcp.approx.f32 %0, %1;" : "=f"(y) : "f"(x)); return y;
}
__device__ __forceinline__ float ex2_fast(float x) {
    float y; asm("ex2.approx.f32 %0, %1;" : "=f"(y) : "f"(x)); return y;
}

#define TWO_LOG2E 2.885390081777927f   // 2 * log2(e)

// tanh(s+e) = 1 - 2/(1 + exp(2s)exp(2e)),  x = 1 + A*B
// Pairing consecutive d's:  v0/x0 + v1/x1 = (v0*x1 + v1*x0) * rcp(x0*x1)
// => ONE MUFU rcp per TWO d-contributions; everything else scalar FFMA/FMUL.
// out = vsum - 2 * Σ_d v_d / x_d
//
// Paired float4 layout (proven R11/R13): word [d2][rowpair] holds
//   ( A(2d2, 2rp), A(2d2, 2rp+1), A(2d2+1, 2rp), A(2d2+1, 2rp+1) )
__global__ __launch_bounds__(THREADS)
void Add_Attn_Layer_59055800320841_kernel(const float* __restrict__ S,
                                          const float* __restrict__ E,
                                          const float* __restrict__ V,
                                          float* __restrict__ out) {
    __shared__ float4 Ap[(D_ / 2) * (TILE / 2)];   // exp(2s), paired (16 KB)
    __shared__ float4 Bp[(D_ / 2) * (TILE / 2)];   // exp(2e), paired (16 KB)
    __shared__ float2 vp[D_ / 2];
    __shared__ float  vsum_s;

    const int bc = blockIdx.z;            // b*C + c   (0..15)
    const int i0 = blockIdx.y * TILE;
    const int j0 = blockIdx.x * TILE;

    const float* Sbase = S + (size_t)bc * L_ * D_ + (size_t)i0 * D_;
    const float* Ebase = E + (size_t)bc * L_ * D_ + (size_t)j0 * D_;

    const int tid = threadIdx.x;

    if (tid < D_ / 2) {
        vp[tid] = *reinterpret_cast<const float2*>(V + 2 * tid);
    }
    if (tid < 32) {
        float s = V[tid] + V[tid + 32] + V[tid + 64] + V[tid + 96];
        #pragma unroll
        for (int o = 16; o > 0; o >>= 1) s += __shfl_xor_sync(0xffffffffu, s, o);
        if (tid == 0) vsum_s = s;
    }

    // Load + transpose + exponentiate into the paired float4 layout.
    float* Apf = reinterpret_cast<float*>(Ap);
    float* Bpf = reinterpret_cast<float*>(Bp);
    #pragma unroll
    for (int idx = tid; idx < TILE * (D_ / 4); idx += THREADS) {
        const int row = idx & (TILE - 1);
        const int d4  = idx >> 5;                 // d = 4*d4 + q
        const float4 sv = *reinterpret_cast<const float4*>(Sbase + row * D_ + d4 * 4);
        const float4 ev = *reinterpret_cast<const float4*>(Ebase + row * D_ + d4 * 4);
        const int rp = row >> 1, rb = row & 1;
        #pragma unroll
        for (int q = 0; q < 4; q++) {
            const int d2  = 2 * d4 + (q >> 1);
            const int off = (d2 * (TILE / 2) + rp) * 4 + (q & 1) * 2 + rb;
            const float fs = (q == 0) ? sv.x : (q == 1) ? sv.y : (q == 2) ? sv.z : sv.w;
            const float fe = (q == 0) ? ev.x : (q == 1) ? ev.y : (q == 2) ? ev.z : ev.w;
            Apf[off] = ex2_fast(fs * TWO_LOG2E);
            Bpf[off] = ex2_fast(fe * TWO_LOG2E);
        }
    }
    __syncthreads();

    // Thread -> 4 rows (4*ti2 .. 4*ti2+3) x 2 cols (2*tj, 2*tj+1)
    const int tj  = tid & 15;
    const int ti2 = tid >> 4;          // 0..7

    // acc[r][c] = Σ_d v_d / x_d  for this thread's 4x2 cells
    float acc00 = 0.f, acc01 = 0.f;
    float acc10 = 0.f, acc11 = 0.f;
    float acc20 = 0.f, acc21 = 0.f;
    float acc30 = 0.f, acc31 = 0.f;

    const float4* ap = Ap + 2 * ti2;   // row-pairs 2*ti2, 2*ti2+1
    const float4* bp = Bp + tj;

    #pragma unroll 4
    for (int d2 = 0; d2 < D_ / 2; d2++) {
        const float4 a0 = ap[d2 * (TILE / 2)];       // rows 4*ti2, 4*ti2+1 (ev: x,y / od: z,w)
        const float4 a1 = ap[d2 * (TILE / 2) + 1];   // rows 4*ti2+2, 4*ti2+3
        const float4 b  = bp[d2 * (TILE / 2)];       // cols 2tj, 2tj+1 (ev: x,y / od: z,w)
        const float2 v2 = vp[d2];

        // cell(ae, ao, be, bo): v0/x0 + v1/x1 with one rcp
        #define CELL(ae, ao, be, bo, ACC) do {                          \
            const float x0 = fmaf((ae), (be), 1.0f);                    \
            const float x1 = fmaf((ao), (bo), 1.0f);                    \
            const float P  = fmaf(v2.x, x1, v2.y * x0);                 \
            (ACC) = fmaf(P, rcp_fast(x0 * x1), (ACC));                  \
        } while (0)

        CELL(a0.x, a0.z, b.x, b.z, acc00);
        CELL(a0.x, a0.z, b.y, b.w, acc01);
        CELL(a0.y, a0.w, b.x, b.z, acc10);
        CELL(a0.y, a0.w, b.y, b.w, acc11);
        CELL(a1.x, a1.z, b.x, b.z, acc20);
        CELL(a1.x, a1.z, b.y, b.w, acc21);
        CELL(a1.y, a1.w, b.x, b.z, acc30);
        CELL(a1.y, a1.w, b.y, b.w, acc31);
        #undef CELL
    }

    // out = vsum - 2 * acc
    const float vsum = vsum_s;

    const int b = bc >> 3;
    const int c = bc & 7;
    const int i = i0 + 4 * ti2;
    const int j = j0 + 2 * tj;
    float* o = out + (((size_t)b * L_ + i) * L_ + j) * C_ + c;
    const size_t rs = (size_t)L_ * C_;   // i -> i+1
    o[0 * rs]      = fmaf(-2.0f, acc00, vsum);
    o[0 * rs + C_] = fmaf(-2.0f, acc01, vsum);
    o[1 * rs]      = fmaf(-2.0f, acc10, vsum);
    o[1 * rs + C_] = fmaf(-2.0f, acc11, vsum);
    o[2 * rs]      = fmaf(-2.0f, acc20, vsum);
    o[2 * rs + C_] = fmaf(-2.0f, acc21, vsum);
    o[3 * rs]      = fmaf(-2.0f, acc30, vsum);
    o[3 * rs + C_] = fmaf(-2.0f, acc31, vsum);
}

extern "C" void kernel_launch(void* const* d_in, const int* in_sizes, int n_in,
                              void* d_out, int out_size) {
    (void)in_sizes; (void)n_in; (void)out_size;
    const float* S = (const float*)d_in[0];   // start_hidden [B,C,L,D]
    const float* E = (const float*)d_in[1];   // end_hidden   [B,C,L,D]
    const float* V = (const float*)d_in[2];   // v [D]
    float* out = (float*)d_out;               // [B,L,L,C] float32

    dim3 grid(L_ / TILE, L_ / TILE, B_ * C_); // (8, 8, 16) = 1024 blocks
    Add_Attn_Layer_59055800320841_kernel<<<grid, THREADS>>>(S, E, V, out);
}

// round 16
// speedup vs baseline: 1.0713x; 1.0713x over previous
#include <cuda_runtime.h>

// Problem constants (fixed by the reference: B=2, C=8, L=256, D=128)
#define B_  2
#define C_  8
#define L_  256
#define D_  128
#define TILE 32          // 32x32 output tile per block
#define THREADS 256      // 16 (ti: row-pairs) x 16 (tj: col-pairs); 2x2 out each

__device__ __forceinline__ float rcp_fast(float x) {
    float y; asm("rcp.approx.f32 %0, %1;" : "=f"(y) : "f"(x)); return y;
}
__device__ __forceinline__ float ex2_fast(float x) {
    float y; asm("ex2.approx.f32 %0, %1;" : "=f"(y) : "f"(x)); return y;
}

#define TWO_LOG2E 2.885390081777927f   // 2 * log2(e)

// tanh(s+e) = 1 - 2/(1 + exp(2s)exp(2e)),  x = 1 + A*B
// Pairing consecutive d's:  v0/x0 + v1/x1 = (v0*x1 + v1*x0) * rcp(x0*x1)
// => ONE MUFU rcp per TWO d-contributions.  out = vsum - 2 * Σ_d v_d / x_d
//
// Paired float4 layout: word [d2][rowpair] = ( A(2d2,2rp), A(2d2,2rp+1),
//                                              A(2d2+1,2rp), A(2d2+1,2rp+1) )
__global__ __launch_bounds__(THREADS)
void Add_Attn_Layer_59055800320841_kernel(const float* __restrict__ S,
                                          const float* __restrict__ E,
                                          const float* __restrict__ V,
                                          float* __restrict__ out) {
    __shared__ float4 Ap[(D_ / 2) * (TILE / 2)];   // exp(2s), paired (16 KB)
    __shared__ float4 Bp[(D_ / 2) * (TILE / 2)];   // exp(2e), paired (16 KB)
    __shared__ float2 vp[D_ / 2];
    __shared__ float  vsum_s;

    const int bc = blockIdx.z;            // b*C + c   (0..15)
    const int i0 = blockIdx.y * TILE;
    const int j0 = blockIdx.x * TILE;

    const float* Sbase = S + (size_t)bc * L_ * D_ + (size_t)i0 * D_;
    const float* Ebase = E + (size_t)bc * L_ * D_ + (size_t)j0 * D_;

    const int tid = threadIdx.x;

    if (tid < D_ / 2) {
        vp[tid] = *reinterpret_cast<const float2*>(V + 2 * tid);
    }
    if (tid < 32) {
        float s = V[tid] + V[tid + 32] + V[tid + 64] + V[tid + 96];
        #pragma unroll
        for (int o = 16; o > 0; o >>= 1) s += __shfl_xor_sync(0xffffffffu, s, o);
        if (tid == 0) vsum_s = s;
    }

    // Load + transpose + exponentiate into the paired float4 layout.
    float* Apf = reinterpret_cast<float*>(Ap);
    float* Bpf = reinterpret_cast<float*>(Bp);
    #pragma unroll
    for (int idx = tid; idx < TILE * (D_ / 4); idx += THREADS) {
        const int row = idx & (TILE - 1);
        const int d4  = idx >> 5;                 // d = 4*d4 + q
        const float4 sv = *reinterpret_cast<const float4*>(Sbase + row * D_ + d4 * 4);
        const float4 ev = *reinterpret_cast<const float4*>(Ebase + row * D_ + d4 * 4);
        const int rp = row >> 1, rb = row & 1;
        #pragma unroll
        for (int q = 0; q < 4; q++) {
            const int d2  = 2 * d4 + (q >> 1);
            const int off = (d2 * (TILE / 2) + rp) * 4 + (q & 1) * 2 + rb;
            const float fs = (q == 0) ? sv.x : (q == 1) ? sv.y : (q == 2) ? sv.z : sv.w;
            const float fe = (q == 0) ? ev.x : (q == 1) ? ev.y : (q == 2) ? ev.z : ev.w;
            Apf[off] = ex2_fast(fs * TWO_LOG2E);
            Bpf[off] = ex2_fast(fe * TWO_LOG2E);
        }
    }
    __syncthreads();

    // Thread -> 2 rows (2*ti, 2*ti+1) x 2 cols (2*tj, 2*tj+1)
    const int tj = tid & 15;
    const int ti = tid >> 4;

    float acc00 = 0.f, acc01 = 0.f, acc10 = 0.f, acc11 = 0.f;

    const float4* ap = Ap + ti;
    const float4* bp = Bp + tj;

    #pragma unroll 2
    for (int d2 = 0; d2 < D_ / 2; d2++) {
        // Decompose immediately so the float4 registers die fast (reg pressure).
        const float4 a4 = ap[d2 * (TILE / 2)];
        const float ae0 = a4.x, ae1 = a4.y, ao0 = a4.z, ao1 = a4.w;
        const float4 b4 = bp[d2 * (TILE / 2)];
        const float be0 = b4.x, be1 = b4.y, bo0 = b4.z, bo1 = b4.w;
        const float2 v2 = vp[d2];
        const float v0 = v2.x, v1 = v2.y;

        {   // cell (r0, c0)
            const float x0 = fmaf(ae0, be0, 1.0f);
            const float x1 = fmaf(ao0, bo0, 1.0f);
            const float P  = fmaf(v0, x1, v1 * x0);
            acc00 = fmaf(P, rcp_fast(x0 * x1), acc00);
        }
        {   // cell (r0, c1)
            const float x0 = fmaf(ae0, be1, 1.0f);
            const float x1 = fmaf(ao0, bo1, 1.0f);
            const float P  = fmaf(v0, x1, v1 * x0);
            acc01 = fmaf(P, rcp_fast(x0 * x1), acc01);
        }
        {   // cell (r1, c0)
            const float x0 = fmaf(ae1, be0, 1.0f);
            const float x1 = fmaf(ao1, bo0, 1.0f);
            const float P  = fmaf(v0, x1, v1 * x0);
            acc10 = fmaf(P, rcp_fast(x0 * x1), acc10);
        }
        {   // cell (r1, c1)
            const float x0 = fmaf(ae1, be1, 1.0f);
            const float x1 = fmaf(ao1, bo1, 1.0f);
            const float P  = fmaf(v0, x1, v1 * x0);
            acc11 = fmaf(P, rcp_fast(x0 * x1), acc11);
        }
    }

    // out = vsum - 2 * acc
    const float vsum = vsum_s;

    const int b = bc >> 3;
    const int c = bc & 7;
    const int i = i0 + 2 * ti;
    const int j = j0 + 2 * tj;
    float* o = out + (((size_t)b * L_ + i) * L_ + j) * C_ + c;
    const size_t rs = (size_t)L_ * C_;   // i -> i+1
    o[0]       = fmaf(-2.0f, acc00, vsum);
    o[C_]      = fmaf(-2.0f, acc01, vsum);
    o[rs]      = fmaf(-2.0f, acc10, vsum);
    o[rs + C_] = fmaf(-2.0f, acc11, vsum);
}

extern "C" void kernel_launch(void* const* d_in, const int* in_sizes, int n_in,
                              void* d_out, int out_size) {
    (void)in_sizes; (void)n_in; (void)out_size;
    const float* S = (const float*)d_in[0];   // start_hidden [B,C,L,D]
    const float* E = (const float*)d_in[1];   // end_hidden   [B,C,L,D]
    const float* V = (const float*)d_in[2];   // v [D]
    float* out = (float*)d_out;               // [B,L,L,C] float32

    dim3 grid(L_ / TILE, L_ / TILE, B_ * C_); // (8, 8, 16) = 1024 blocks
    Add_Attn_Layer_59055800320841_kernel<<<grid, THREADS>>>(S, E, V, out);
}

// round 17
// speedup vs baseline: 1.1948x; 1.1152x over previous
#include <cuda_runtime.h>

// Problem constants (fixed by the reference: B=2, C=8, L=256, D=128)
#define B_  2
#define C_  8
#define L_  256
#define D_  128
#define TILE 32          // 32x32 output tile per block
#define THREADS 512      // 16 (ti: row-pairs) x 32 (tj: cols); 2x1 outputs each

__device__ __forceinline__ float tanh_fast(float x) {
    float y; asm("tanh.approx.f32 %0, %1;" : "=f"(y) : "f"(x)); return y;
}

// A: paired float4 [d2][rowpair] = ( s(2d2,2rp), s(2d2,2rp+1),
//                                    s(2d2+1,2rp), s(2d2+1,2rp+1) )
//    -> whole-warp broadcast LDS.128 (all lanes in a warp share ti).
// B: float2 [d2][col] = ( e(2d2,col), e(2d2+1,col) )
//    -> 32 consecutive float2 per warp, conflict-free LDS.64.
__global__ __launch_bounds__(THREADS)
void Add_Attn_Layer_59055800320841_kernel(const float* __restrict__ S,
                                          const float* __restrict__ E,
                                          const float* __restrict__ V,
                                          float* __restrict__ out) {
    __shared__ float4 Ap[(D_ / 2) * (TILE / 2)];   // s paired      (16 KB)
    __shared__ float2 Bp[(D_ / 2) * TILE];         // e d2-pairs    (16 KB)
    __shared__ float2 vp[D_ / 2];

    const int bc = blockIdx.z;            // b*C + c   (0..15)
    const int i0 = blockIdx.y * TILE;
    const int j0 = blockIdx.x * TILE;

    const float* Sbase = S + (size_t)bc * L_ * D_ + (size_t)i0 * D_;
    const float* Ebase = E + (size_t)bc * L_ * D_ + (size_t)j0 * D_;

    const int tid = threadIdx.x;

    if (tid < D_ / 2) {
        vp[tid] = *reinterpret_cast<const float2*>(V + 2 * tid);
    }

    // Load + transpose (raw values, no math).
    float* Apf = reinterpret_cast<float*>(Ap);
    #pragma unroll
    for (int idx = tid; idx < TILE * (D_ / 4); idx += THREADS) {
        const int row = idx & (TILE - 1);
        const int d4  = idx >> 5;                 // d = 4*d4 + q
        const float4 sv = *reinterpret_cast<const float4*>(Sbase + row * D_ + d4 * 4);
        const float4 ev = *reinterpret_cast<const float4*>(Ebase + row * D_ + d4 * 4);
        const int rp = row >> 1, rb = row & 1;
        // A: paired float4 layout
        {
            const int d2a = 2 * d4;       // covers d = 4d4, 4d4+1
            const int d2b = 2 * d4 + 1;   // covers d = 4d4+2, 4d4+3
            Apf[(d2a * (TILE / 2) + rp) * 4 + 0 * 2 + rb] = sv.x;
            Apf[(d2a * (TILE / 2) + rp) * 4 + 1 * 2 + rb] = sv.y;
            Apf[(d2b * (TILE / 2) + rp) * 4 + 0 * 2 + rb] = sv.z;
            Apf[(d2b * (TILE / 2) + rp) * 4 + 1 * 2 + rb] = sv.w;
        }
        // B: [d2][col] float2 (col == row index here)
        Bp[(2 * d4 + 0) * TILE + row] = make_float2(ev.x, ev.y);
        Bp[(2 * d4 + 1) * TILE + row] = make_float2(ev.z, ev.w);
    }
    __syncthreads();

    // Thread -> rows (2*ti, 2*ti+1) x col tj
    const int tj = tid & 31;
    const int ti = tid >> 5;

    float a0 = 0.f, a1 = 0.f;

    const float4* ap = Ap + ti;
    const float2* bp = Bp + tj;

    #pragma unroll 8
    for (int d2 = 0; d2 < D_ / 2; d2++) {
        const float4 s4 = ap[d2 * (TILE / 2)];   // (sd0_r0, sd0_r1, sd1_r0, sd1_r1)
        const float2 e2 = bp[d2 * TILE];         // (ed0_c, ed1_c)
        const float2 v2 = vp[d2];
        // d = 2*d2
        a0 = fmaf(v2.x, tanh_fast(s4.x + e2.x), a0);
        a1 = fmaf(v2.x, tanh_fast(s4.y + e2.x), a1);
        // d = 2*d2+1
        a0 = fmaf(v2.y, tanh_fast(s4.z + e2.y), a0);
        a1 = fmaf(v2.y, tanh_fast(s4.w + e2.y), a1);
    }

    // out[b][i][j][c], c fastest; bc = b*C + c
    const int b = bc >> 3;
    const int c = bc & 7;
    const int i = i0 + 2 * ti;
    const int j = j0 + tj;
    float* o = out + (((size_t)b * L_ + i) * L_ + j) * C_ + c;
    const size_t rs = (size_t)L_ * C_;   // i -> i+1
    o[0]  = a0;
    o[rs] = a1;
}

extern "C" void kernel_launch(void* const* d_in, const int* in_sizes, int n_in,
                              void* d_out, int out_size) {
    (void)in_sizes; (void)n_in; (void)out_size;
    const float* S = (const float*)d_in[0];   // start_hidden [B,C,L,D]
    const float* E = (const float*)d_in[1];   // end_hidden   [B,C,L,D]
    const float* V = (const float*)d_in[2];   // v [D]
    float* out = (float*)d_out;               // [B,L,L,C] float32

    dim3 grid(L_ / TILE, L_ / TILE, B_ * C_); // (8, 8, 16) = 1024 blocks
    Add_Attn_Layer_59055800320841_kernel<<<grid, THREADS>>>(S, E, V, out);
}